// round 14
// baseline (speedup 1.0000x reference)
#include <cuda_runtime.h>
#include <cuda_fp16.h>
#include <cstdint>
#include <cstddef>
#include <cstring>

#define B_  64
#define S_  512
#define E_  1024
#define H_  1024
#define NG  4096
#define NCTA 128

typedef unsigned long long ull;

// ---------------- device scratch ----------------
__device__ __half g_xg16[(size_t)S_ * B_ * NG];   // [t][b][n] fp16 gate preacts
__device__ __half g_xh[(size_t)B_ * S_ * E_];     // x in fp16
__device__ __half g_wh[(size_t)NG * E_];          // Wx in fp16, [gate-major n][k]
__device__ __half g_hh[2][B_ * H_];               // hidden state fp16, [b][k]
__device__ unsigned g_bar_count = 0;
__device__ unsigned g_bar_gen   = 0;
__device__ unsigned g_pflags[NCTA * 64];          // producer: h for step t+1 written
__device__ unsigned g_rflags[NCTA * 64];          // consumer: staging reads of step t done

// ---------------- helpers ----------------
__device__ __forceinline__ uint32_t smem_u32(const void* p) {
    uint32_t a;
    asm("{ .reg .u64 t; cvta.to.shared.u64 t, %1; cvt.u32.u64 %0, t; }" : "=r"(a) : "l"(p));
    return a;
}
__device__ __forceinline__ void cpa16(uint32_t saddr, const void* g) {
    asm volatile("cp.async.cg.shared.global [%0], [%1], 16;" :: "r"(saddr), "l"(g) : "memory");
}
__device__ __forceinline__ void cpa_commit() {
    asm volatile("cp.async.commit_group;" ::: "memory");
}
template<int N> __device__ __forceinline__ void cpa_wait() {
    asm volatile("cp.async.wait_group %0;" :: "n"(N) : "memory");
}
__device__ __forceinline__ void ldmx4(uint32_t* r, uint32_t addr) {
    asm volatile("ldmatrix.sync.aligned.m8n8.x4.shared.b16 {%0,%1,%2,%3}, [%4];"
        : "=r"(r[0]), "=r"(r[1]), "=r"(r[2]), "=r"(r[3]) : "r"(addr));
}
__device__ __forceinline__ void mma16(float* d, const uint32_t* a, const uint32_t* b) {
    asm("mma.sync.aligned.m16n8k16.row.col.f32.f16.f16.f32 "
        "{%0,%1,%2,%3}, {%4,%5,%6,%7}, {%8,%9}, {%0,%1,%2,%3};"
        : "+f"(d[0]), "+f"(d[1]), "+f"(d[2]), "+f"(d[3])
        : "r"(a[0]), "r"(a[1]), "r"(a[2]), "r"(a[3]), "r"(b[0]), "r"(b[1]));
}
__device__ __forceinline__ uint32_t mapa_u32(uint32_t a, uint32_t rank) {
    uint32_t r;
    asm("mapa.shared::cluster.u32 %0, %1, %2;" : "=r"(r) : "r"(a), "r"(rank));
    return r;
}
__device__ __forceinline__ void stc64(uint32_t addr, ull v) {
    asm volatile("st.shared::cluster.b64 [%0], %1;" :: "r"(addr), "l"(v) : "memory");
}
#define CLUSTER_SYNC() do { \
    asm volatile("barrier.cluster.arrive.aligned;" ::: "memory"); \
    asm volatile("barrier.cluster.wait.aligned;"   ::: "memory"); } while (0)

__device__ __forceinline__ float sigm(float z) { return 1.f / (1.f + expf(-z)); }

// Atomic barrier — used only at init (replay-safe, proven).
__device__ __forceinline__ void grid_barrier() {
    __syncthreads();
    if (threadIdx.x == 0) {
        __threadfence();
        unsigned gen = *(volatile unsigned*)&g_bar_gen;
        if (atomicAdd(&g_bar_count, 1u) == NCTA - 1) {
            atomicExch(&g_bar_count, 0u);
            __threadfence();
            atomicAdd(&g_bar_gen, 1u);
        } else {
            while (*(volatile unsigned*)&g_bar_gen == gen) __nanosleep(32);
        }
        __threadfence();
    }
    __syncthreads();
}

// ===========================================================================
// Kernel 0: convert x and Wx (x-part columns) to fp16 scratch. Unchanged.
// ===========================================================================
__global__ void convert_h(
    const float* __restrict__ x,
    const float* __restrict__ Wf, const float* __restrict__ Wi,
    const float* __restrict__ Wc, const float* __restrict__ Wo)
{
    const int stride = gridDim.x * blockDim.x;
    const int i0 = blockIdx.x * blockDim.x + threadIdx.x;
    const int NX = B_ * S_ * E_ / 2;
    for (int i = i0; i < NX; i += stride) {
        float2 v = *(const float2*)(x + (size_t)2 * i);
        ((__half2*)g_xh)[i] = __floats2half2_rn(v.x, v.y);
    }
    const int NW = NG * E_ / 2;
    for (int i = i0; i < NW; i += stride) {
        int n = i >> 9, k2 = i & 511;
        const float* Ws = (n < 1024) ? Wf : (n < 2048) ? Wi : (n < 3072) ? Wc : Wo;
        float2 v = *(const float2*)(Ws + (size_t)(n & 1023) * 2048 + k2 * 2);
        ((__half2*)g_wh)[i] = __floats2half2_rn(v.x, v.y);
    }
}

// ===========================================================================
// Phase 1: Xg = x @ Wx^T (fp16 mma, ldmatrix, cp.async 3-stage). Unchanged.
// ===========================================================================
#define P1_STAGE 36864
#define P1_SMEM  (3 * P1_STAGE)

__device__ __forceinline__ void p1_issue(uint32_t sb, int m0, int n0, int k0, int tid) {
    const int r = tid >> 3, c = tid & 7;
#pragma unroll
    for (int j = 0; j < 4; j++) {
        int rr = r + j * 32;
        cpa16(sb + rr * 144 + c * 16,         g_xh + (size_t)(m0 + rr) * E_ + k0 + c * 8);
        cpa16(sb + 18432 + rr * 144 + c * 16, g_wh + (size_t)(n0 + rr) * E_ + k0 + c * 8);
    }
    cpa_commit();
}

__global__ void __launch_bounds__(256, 2) xgemm_h()
{
    extern __shared__ char sm[];
    const uint32_t smb = smem_u32(sm);

    const int tid = threadIdx.x;
    const int wid = tid >> 5, lane = tid & 31;
    const int gid = lane >> 2, tg = lane & 3;
    const int wm = wid >> 2, wn = wid & 3;
    const int m0 = blockIdx.y * 128;
    const int n0 = blockIdx.x * 128;

    uint32_t laneA[4], laneB[2];
#pragma unroll
    for (int mi = 0; mi < 4; mi++)
        laneA[mi] = (wm * 64 + mi * 16 + ((lane >> 3) & 1) * 8 + (lane & 7)) * 144
                  + (lane >> 4) * 16;
#pragma unroll
    for (int p = 0; p < 2; p++)
        laneB[p] = 18432
                 + (wn * 32 + p * 16 + (lane >> 4) * 8 + (lane & 7)) * 144
                 + ((lane >> 3) & 1) * 16;

    float acc[4][4][4];
#pragma unroll
    for (int i = 0; i < 4; i++)
#pragma unroll
        for (int j = 0; j < 4; j++)
#pragma unroll
            for (int k = 0; k < 4; k++) acc[i][j][k] = 0.f;

    p1_issue(smb, m0, n0, 0, tid);
    p1_issue(smb + P1_STAGE, m0, n0, 64, tid);

    int st = 0;
    for (int ch = 0; ch < 16; ch++) {
        if (ch < 15) cpa_wait<1>(); else cpa_wait<0>();
        __syncthreads();
        if (ch + 2 < 16) {
            int st2 = st + 2; if (st2 >= 3) st2 -= 3;
            p1_issue(smb + st2 * P1_STAGE, m0, n0, (ch + 2) * 64, tid);
        }
        const uint32_t sb = smb + st * P1_STAGE;
#pragma unroll
        for (int kk = 0; kk < 4; kk++) {
            uint32_t a[4][4], b[2][4];
#pragma unroll
            for (int mi = 0; mi < 4; mi++) ldmx4(a[mi], sb + laneA[mi] + kk * 32);
#pragma unroll
            for (int p = 0; p < 2; p++)   ldmx4(b[p],  sb + laneB[p] + kk * 32);
#pragma unroll
            for (int mi = 0; mi < 4; mi++)
#pragma unroll
                for (int ni = 0; ni < 4; ni++)
                    mma16(acc[mi][ni], a[mi], b[ni >> 1] + (ni & 1) * 2);
        }
        if (++st >= 3) st -= 3;
    }

    // epilogue: frags -> g_xg16[t][b][n] (fp16)
#pragma unroll
    for (int mi = 0; mi < 4; mi++) {
        int row = m0 + wm * 64 + mi * 16 + gid;
        int b = row >> 9, t = row & (S_ - 1);
#pragma unroll
        for (int ni = 0; ni < 4; ni++) {
            int col = n0 + wn * 32 + ni * 8 + tg * 2;
            __half* p0 = g_xg16 + ((size_t)t * B_ + b) * NG + col;
            __half* p1 = g_xg16 + ((size_t)(t + 8) * B_ + b) * NG + col;
            *(__half2*)p0 = __floats2half2_rn(acc[mi][ni][0], acc[mi][ni][1]);
            *(__half2*)p1 = __floats2half2_rn(acc[mi][ni][2], acc[mi][ni][3]);
        }
    }
}

// ===========================================================================
// Phase 2: persistent scan, fp16 mma, cluster-pair K-split,
// R13: NO per-step grid barrier — producer/consumer flags per K-chunk,
// chunk polls interleaved with MMA; double-buffered DSMEM red.
// ===========================================================================
#define HROW2   1040                      // 512 halves + 16B pad
#define WH_OFF  0                         // 64*1040 = 66560
#define AB_OFF  66560                     // 64*1040 -> 133120
#define RED_OFF 133120                    // 2 x [64][34] f32 = 17408 -> 150528
#define ZB_OFF  150528                    // [64][34] f32 -> 159232
#define CS_OFF  159232                    // 2048 -> 161280
#define BS_OFF  161280                    // 128  -> 161408
#define P2_SMEM 161408
#define REDSLOT 2176                      // floats per red slot

__global__ void __launch_bounds__(256, 1) __cluster_dims__(2, 1, 1) lstm_seq_h(
    const float* __restrict__ Wf, const float* __restrict__ bf,
    const float* __restrict__ Wi, const float* __restrict__ bi,
    const float* __restrict__ Wc, const float* __restrict__ bc,
    const float* __restrict__ Wo, const float* __restrict__ bo,
    float* __restrict__ out)
{
    extern __shared__ char sm[];
    float* red = (float*)(sm + RED_OFF);
    float* zbf = (float*)(sm + ZB_OFF);
    float* csm = (float*)(sm + CS_OFF);
    float* bsm = (float*)(sm + BS_OFF);

    const int tid = threadIdx.x;
    const int wid = tid >> 5, lane = tid & 31;
    const int gid = lane >> 2, tg = lane & 3;
    const int mi = wid >> 1, ns = wid & 1;
    const int cta = blockIdx.x;
    const int krank = cta & 1;                  // cluster rank == K-half
    const int pcta = cta ^ 1;
    const int pbase = krank * 64;               // producers of my K-half
    const float* Wp[4] = {Wf, Wi, Wc, Wo};
    const float* bp[4] = {bf, bi, bc, bo};

    // one-time: Wh -> SMEM fp16. rows 0-31 = own cols, 32-63 = partner cols.
    for (int idx = tid; idx < 64 * 256; idx += 256) {
        int n = idx >> 8, k2 = idx & 255;
        int colset = (n < 32) ? cta : pcta;
        int nn = n & 31;
        const float* wr = Wp[nn >> 3]
            + (size_t)(colset * 8 + (nn & 7)) * 2048 + 1024 + krank * 512 + k2 * 2;
        float2 v = *(const float2*)wr;
        *(__half2*)(sm + WH_OFF + n * HROW2 + k2 * 4) = __floats2half2_rn(v.x, v.y);
    }
    if (tid < 32) bsm[tid] = bp[tid >> 3][cta * 8 + (tid & 7)];
    if (tid == 0) {
        *(volatile unsigned*)&g_pflags[cta * 64] = 0u;   // replay-safe reset
        *(volatile unsigned*)&g_rflags[cta * 64] = 0u;
    }
    for (int i = tid; i < 512; i += 256) {
        csm[i] = 0.f;
        g_hh[0][(i >> 3) * H_ + cta * 8 + (i & 7)] = __float2half(0.f);
    }
    __syncthreads();
    grid_barrier();       // h0 + flag resets visible everywhere

    const uint32_t abBase = smem_u32(sm + AB_OFF);
    const uint32_t whBase = smem_u32(sm + WH_OFF);
    const uint32_t aA = abBase
        + (mi * 16 + ((lane >> 3) & 1) * 8 + (lane & 7)) * HROW2 + (lane >> 4) * 16;
    uint32_t laneB[2];
#pragma unroll
    for (int p = 0; p < 2; p++)
        laneB[p] = whBase
            + (ns * 32 + p * 16 + (lane >> 4) * 8 + (lane & 7)) * HROW2
            + ((lane >> 3) & 1) * 16;
    const uint32_t peer_red = mapa_u32(smem_u32(red), (uint32_t)(krank ^ 1));

#define WAIT_PROD(g) do { \
    if (wid == 0) { \
        if (lane < 16) \
            while (*(volatile unsigned*)&g_pflags[(pbase + (g) * 16 + lane) * 64] < tv) {} \
        __threadfence(); \
    } \
} while (0)

#define ISSUE_CHUNK(g) do { \
    _Pragma("unroll") \
    for (int j = 0; j < 4; j++) { \
        int idx = tid + j * 256; \
        int r = idx >> 4, c = idx & 15; \
        cpa16(abBase + r * HROW2 + (g) * 256 + c * 16, \
              hcur + r * H_ + krank * 512 + (g) * 128 + c * 8); \
    } \
    cpa_commit(); \
} while (0)

#define MMA_GROUP(g) do { \
    _Pragma("unroll") \
    for (int ksl = 0; ksl < 8; ksl++) { \
        const uint32_t koff = (uint32_t)((g) * 8 + ksl) * 32; \
        uint32_t a[4], b0v[4], b1v[4]; \
        ldmx4(a,   aA + koff); \
        ldmx4(b0v, laneB[0] + koff); \
        ldmx4(b1v, laneB[1] + koff); \
        mma16(acc[0], a, b0v); \
        mma16(acc[1], a, b0v + 2); \
        mma16(acc[2], a, b1v); \
        mma16(acc[3], a, b1v + 2); \
    } \
} while (0)

    for (int t = 0; t < S_; t++) {
        const __half* hcur = g_hh[t & 1];
        const unsigned tv = (unsigned)t;
        float* reds = red + (t & 1) * REDSLOT;
        const uint32_t peer_reds = peer_red + (uint32_t)((t & 1) * REDSLOT * 4);

        // reverse wait (warp 1): all consumers done reading buffer (t+1)&1
        if (wid == 1) {
            for (int j = 0; j < 4; j++)
                while (*(volatile unsigned*)&g_rflags[(lane * 4 + j) * 64] < tv) {}
            __threadfence();
        }
        WAIT_PROD(0);
        __syncthreads();
        ISSUE_CHUNK(0);

        // prefetch xg (fp16, overlaps staging + MMA)
        float xpf[2][4];
#pragma unroll
        for (int q = 0; q < 2; q++) {
            int i = tid + q * 256;
            int b = i >> 3, r = i & 7;
            const __half* xgb = g_xg16 + ((size_t)t * B_ + b) * NG + cta * 8 + r;
            xpf[q][0] = __half2float(__ldg(xgb));
            xpf[q][1] = __half2float(__ldg(xgb + 1024));
            xpf[q][2] = __half2float(__ldg(xgb + 2048));
            xpf[q][3] = __half2float(__ldg(xgb + 3072));
        }

        WAIT_PROD(1);
        __syncthreads();
        ISSUE_CHUNK(1);

        float acc[4][4];
#pragma unroll
        for (int i = 0; i < 4; i++)
#pragma unroll
            for (int k = 0; k < 4; k++) acc[i][k] = 0.f;

        cpa_wait<1>(); __syncthreads();
        MMA_GROUP(0);

        WAIT_PROD(2);
        __syncthreads();
        ISSUE_CHUNK(2);
        cpa_wait<1>(); __syncthreads();
        MMA_GROUP(1);

        WAIT_PROD(3);
        __syncthreads();
        ISSUE_CHUNK(3);
        cpa_wait<1>(); __syncthreads();
        MMA_GROUP(2);

        cpa_wait<0>(); __syncthreads();
        // all staging reads of g_hh[t&1] complete -> signal consumers-done early
        if (tid == 0) { __threadfence(); *(volatile unsigned*)&g_rflags[cta * 64] = tv + 1u; }
        MMA_GROUP(3);

        // partials: ns=0 -> local zbf (own cols); ns=1 -> DSMEM to peer red slot
        const int b0r = mi * 16 + gid;
        if (ns == 0) {
#pragma unroll
            for (int nt = 0; nt < 4; nt++) {
                int col = nt * 8 + tg * 2;
                *(float2*)&zbf[b0r * 34 + col]       = make_float2(acc[nt][0], acc[nt][1]);
                *(float2*)&zbf[(b0r + 8) * 34 + col] = make_float2(acc[nt][2], acc[nt][3]);
            }
        } else {
#pragma unroll
            for (int nt = 0; nt < 4; nt++) {
                int col = nt * 8 + tg * 2;
                float2 f0 = make_float2(acc[nt][0], acc[nt][1]);
                float2 f1 = make_float2(acc[nt][2], acc[nt][3]);
                ull v0, v1;
                memcpy(&v0, &f0, 8);
                memcpy(&v1, &f1, 8);
                stc64(peer_reds + (uint32_t)(b0r * 34 + col) * 4, v0);
                stc64(peer_reds + (uint32_t)((b0r + 8) * 34 + col) * 4, v1);
            }
        }
        CLUSTER_SYNC();

        // gate math; c stays in SMEM; h -> fp16 global + fp32 output
        __half* hnext = g_hh[(t + 1) & 1];
#pragma unroll
        for (int q = 0; q < 2; q++) {
            int i = tid + q * 256;
            int b = i >> 3, r = i & 7;
            float zf = zbf[b * 34 + r]      + reds[b * 34 + r]      + bsm[r]      + xpf[q][0];
            float zi = zbf[b * 34 + 8 + r]  + reds[b * 34 + 8 + r]  + bsm[8 + r]  + xpf[q][1];
            float zg = zbf[b * 34 + 16 + r] + reds[b * 34 + 16 + r] + bsm[16 + r] + xpf[q][2];
            float zo = zbf[b * 34 + 24 + r] + reds[b * 34 + 24 + r] + bsm[24 + r] + xpf[q][3];
            float cc = sigm(zf) * csm[i] + sigm(zi) * tanhf(zg);
            csm[i] = cc;
            float h = sigm(zo) * tanhf(cc);
            int hc = cta * 8 + r;
            hnext[b * H_ + hc] = __float2half(h);
            out[((size_t)b * S_ + t) * H_ + hc] = h;
            if (t == S_ - 1) {
                out[(size_t)B_ * S_ * H_ + b * H_ + hc] = h;                    // hT
                out[(size_t)B_ * S_ * H_ + (size_t)B_ * H_ + b * H_ + hc] = cc; // cT
            }
        }
        __syncthreads();
        // h for step t+1 fully written -> signal producers-done
        if (tid == 0) { __threadfence(); *(volatile unsigned*)&g_pflags[cta * 64] = tv + 1u; }
    }
#undef WAIT_PROD
#undef ISSUE_CHUNK
#undef MMA_GROUP
}

// ===========================================================================
extern "C" void kernel_launch(void* const* d_in, const int* in_sizes, int n_in,
                              void* d_out, int out_size) {
    const float* x  = (const float*)d_in[0];
    const float* Wf = (const float*)d_in[1];
    const float* bf = (const float*)d_in[2];
    const float* Wi = (const float*)d_in[3];
    const float* bi = (const float*)d_in[4];
    const float* Wc = (const float*)d_in[5];
    const float* bc = (const float*)d_in[6];
    const float* Wo = (const float*)d_in[7];
    const float* bo = (const float*)d_in[8];
    float* out = (float*)d_out;

    convert_h<<<1024, 256>>>(x, Wf, Wi, Wc, Wo);

    cudaFuncSetAttribute(xgemm_h, cudaFuncAttributeMaxDynamicSharedMemorySize, P1_SMEM);
    dim3 g1(NG / 128, (B_ * S_) / 128);            // (32, 256)
    xgemm_h<<<g1, 256, P1_SMEM>>>();

    cudaFuncSetAttribute(lstm_seq_h, cudaFuncAttributeMaxDynamicSharedMemorySize, P2_SMEM);
    lstm_seq_h<<<NCTA, 256, P2_SMEM>>>(Wf, bf, Wi, bi, Wc, bc, Wo, bo, out);
}

// round 15
// speedup vs baseline: 1.2726x; 1.2726x over previous
#include <cuda_runtime.h>
#include <cuda_fp16.h>
#include <cstdint>
#include <cstddef>
#include <cstring>

#define B_  64
#define S_  512
#define E_  1024
#define H_  1024
#define NG  4096
#define NCTA 128

typedef unsigned long long ull;

// ---------------- device scratch ----------------
__device__ __half g_xg16[(size_t)S_ * B_ * NG];   // [t][b][n] fp16 gate preacts
__device__ __half g_xh[(size_t)B_ * S_ * E_];     // x in fp16
__device__ __half g_wh[(size_t)NG * E_];          // Wx in fp16, [gate-major n][k]
__device__ __half g_hh[2][B_ * H_];               // hidden state fp16, [b][k]
__device__ unsigned g_bar_count = 0;
__device__ unsigned g_bar_gen   = 0;
__device__ unsigned g_flags[NCTA * 64];           // per-CTA step flags, 256B stride

// ---------------- helpers ----------------
__device__ __forceinline__ uint32_t smem_u32(const void* p) {
    uint32_t a;
    asm("{ .reg .u64 t; cvta.to.shared.u64 t, %1; cvt.u32.u64 %0, t; }" : "=r"(a) : "l"(p));
    return a;
}
__device__ __forceinline__ void cpa16(uint32_t saddr, const void* g) {
    asm volatile("cp.async.cg.shared.global [%0], [%1], 16;" :: "r"(saddr), "l"(g) : "memory");
}
__device__ __forceinline__ void cpa_commit() {
    asm volatile("cp.async.commit_group;" ::: "memory");
}
template<int N> __device__ __forceinline__ void cpa_wait() {
    asm volatile("cp.async.wait_group %0;" :: "n"(N) : "memory");
}
__device__ __forceinline__ void ldmx4(uint32_t* r, uint32_t addr) {
    asm volatile("ldmatrix.sync.aligned.m8n8.x4.shared.b16 {%0,%1,%2,%3}, [%4];"
        : "=r"(r[0]), "=r"(r[1]), "=r"(r[2]), "=r"(r[3]) : "r"(addr));
}
__device__ __forceinline__ void mma16(float* d, const uint32_t* a, const uint32_t* b) {
    asm("mma.sync.aligned.m16n8k16.row.col.f32.f16.f16.f32 "
        "{%0,%1,%2,%3}, {%4,%5,%6,%7}, {%8,%9}, {%0,%1,%2,%3};"
        : "+f"(d[0]), "+f"(d[1]), "+f"(d[2]), "+f"(d[3])
        : "r"(a[0]), "r"(a[1]), "r"(a[2]), "r"(a[3]), "r"(b[0]), "r"(b[1]));
}
__device__ __forceinline__ uint32_t mapa_u32(uint32_t a, uint32_t rank) {
    uint32_t r;
    asm("mapa.shared::cluster.u32 %0, %1, %2;" : "=r"(r) : "r"(a), "r"(rank));
    return r;
}
__device__ __forceinline__ void stc64(uint32_t addr, ull v) {
    asm volatile("st.shared::cluster.b64 [%0], %1;" :: "r"(addr), "l"(v) : "memory");
}
#define CLUSTER_SYNC() do { \
    asm volatile("barrier.cluster.arrive.aligned;" ::: "memory"); \
    asm volatile("barrier.cluster.wait.aligned;"   ::: "memory"); } while (0)

__device__ __forceinline__ float sigm(float z) { return 1.f / (1.f + expf(-z)); }

// Atomic barrier — used only at init (replay-safe, proven).
__device__ __forceinline__ void grid_barrier() {
    __syncthreads();
    if (threadIdx.x == 0) {
        __threadfence();
        unsigned gen = *(volatile unsigned*)&g_bar_gen;
        if (atomicAdd(&g_bar_count, 1u) == NCTA - 1) {
            atomicExch(&g_bar_count, 0u);
            __threadfence();
            atomicAdd(&g_bar_gen, 1u);
        } else {
            while (*(volatile unsigned*)&g_bar_gen == gen) __nanosleep(32);
        }
        __threadfence();
    }
    __syncthreads();
}

// ===========================================================================
// Kernel 0: convert x and Wx (x-part columns) to fp16 scratch. Unchanged.
// ===========================================================================
__global__ void convert_h(
    const float* __restrict__ x,
    const float* __restrict__ Wf, const float* __restrict__ Wi,
    const float* __restrict__ Wc, const float* __restrict__ Wo)
{
    const int stride = gridDim.x * blockDim.x;
    const int i0 = blockIdx.x * blockDim.x + threadIdx.x;
    const int NX = B_ * S_ * E_ / 2;
    for (int i = i0; i < NX; i += stride) {
        float2 v = *(const float2*)(x + (size_t)2 * i);
        ((__half2*)g_xh)[i] = __floats2half2_rn(v.x, v.y);
    }
    const int NW = NG * E_ / 2;
    for (int i = i0; i < NW; i += stride) {
        int n = i >> 9, k2 = i & 511;
        const float* Ws = (n < 1024) ? Wf : (n < 2048) ? Wi : (n < 3072) ? Wc : Wo;
        float2 v = *(const float2*)(Ws + (size_t)(n & 1023) * 2048 + k2 * 2);
        ((__half2*)g_wh)[i] = __floats2half2_rn(v.x, v.y);
    }
}

// ===========================================================================
// Phase 1: Xg = x @ Wx^T (fp16 mma, ldmatrix, cp.async 3-stage). Unchanged.
// ===========================================================================
#define P1_STAGE 36864
#define P1_SMEM  (3 * P1_STAGE)

__device__ __forceinline__ void p1_issue(uint32_t sb, int m0, int n0, int k0, int tid) {
    const int r = tid >> 3, c = tid & 7;
#pragma unroll
    for (int j = 0; j < 4; j++) {
        int rr = r + j * 32;
        cpa16(sb + rr * 144 + c * 16,         g_xh + (size_t)(m0 + rr) * E_ + k0 + c * 8);
        cpa16(sb + 18432 + rr * 144 + c * 16, g_wh + (size_t)(n0 + rr) * E_ + k0 + c * 8);
    }
    cpa_commit();
}

__global__ void __launch_bounds__(256, 2) xgemm_h()
{
    extern __shared__ char sm[];
    const uint32_t smb = smem_u32(sm);

    const int tid = threadIdx.x;
    const int wid = tid >> 5, lane = tid & 31;
    const int gid = lane >> 2, tg = lane & 3;
    const int wm = wid >> 2, wn = wid & 3;
    const int m0 = blockIdx.y * 128;
    const int n0 = blockIdx.x * 128;

    uint32_t laneA[4], laneB[2];
#pragma unroll
    for (int mi = 0; mi < 4; mi++)
        laneA[mi] = (wm * 64 + mi * 16 + ((lane >> 3) & 1) * 8 + (lane & 7)) * 144
                  + (lane >> 4) * 16;
#pragma unroll
    for (int p = 0; p < 2; p++)
        laneB[p] = 18432
                 + (wn * 32 + p * 16 + (lane >> 4) * 8 + (lane & 7)) * 144
                 + ((lane >> 3) & 1) * 16;

    float acc[4][4][4];
#pragma unroll
    for (int i = 0; i < 4; i++)
#pragma unroll
        for (int j = 0; j < 4; j++)
#pragma unroll
            for (int k = 0; k < 4; k++) acc[i][j][k] = 0.f;

    p1_issue(smb, m0, n0, 0, tid);
    p1_issue(smb + P1_STAGE, m0, n0, 64, tid);

    int st = 0;
    for (int ch = 0; ch < 16; ch++) {
        if (ch < 15) cpa_wait<1>(); else cpa_wait<0>();
        __syncthreads();
        if (ch + 2 < 16) {
            int st2 = st + 2; if (st2 >= 3) st2 -= 3;
            p1_issue(smb + st2 * P1_STAGE, m0, n0, (ch + 2) * 64, tid);
        }
        const uint32_t sb = smb + st * P1_STAGE;
#pragma unroll
        for (int kk = 0; kk < 4; kk++) {
            uint32_t a[4][4], b[2][4];
#pragma unroll
            for (int mi = 0; mi < 4; mi++) ldmx4(a[mi], sb + laneA[mi] + kk * 32);
#pragma unroll
            for (int p = 0; p < 2; p++)   ldmx4(b[p],  sb + laneB[p] + kk * 32);
#pragma unroll
            for (int mi = 0; mi < 4; mi++)
#pragma unroll
                for (int ni = 0; ni < 4; ni++)
                    mma16(acc[mi][ni], a[mi], b[ni >> 1] + (ni & 1) * 2);
        }
        if (++st >= 3) st -= 3;
    }

    // epilogue: frags -> g_xg16[t][b][n] (fp16)
#pragma unroll
    for (int mi = 0; mi < 4; mi++) {
        int row = m0 + wm * 64 + mi * 16 + gid;
        int b = row >> 9, t = row & (S_ - 1);
#pragma unroll
        for (int ni = 0; ni < 4; ni++) {
            int col = n0 + wn * 32 + ni * 8 + tg * 2;
            __half* p0 = g_xg16 + ((size_t)t * B_ + b) * NG + col;
            __half* p1 = g_xg16 + ((size_t)(t + 8) * B_ + b) * NG + col;
            *(__half2*)p0 = __floats2half2_rn(acc[mi][ni][0], acc[mi][ni][1]);
            *(__half2*)p1 = __floats2half2_rn(acc[mi][ni][2], acc[mi][ni][3]);
        }
    }
}

// ===========================================================================
// Phase 2: persistent scan, fp16 mma, cluster-pair K-split (R12 structure).
// R14 delta: parity-aligned column ownership — CTA c owns gate-cols
// col(c) = (c&1)*512 + (c>>1)*8, which lie inside its own staged K-half.
// Readers of c's h-columns == same-parity CTAs, so the per-step wait covers
// only the 64 same-parity flags. DSMEM red parity double-buffered (partner
// is opposite parity and no longer barrier-coupled).
// ===========================================================================
#define HROW2   1040                      // 512 halves + 16B pad
#define WH_OFF  0                         // 64*1040 = 66560
#define AB_OFF  66560                     // 64*1040 -> 133120
#define RED_OFF 133120                    // 2 x [64][34] f32 -> 150528
#define ZB_OFF  150528                    // [64][34] f32 -> 159232
#define CS_OFF  159232                    // 2048 -> 161280
#define BS_OFF  161280                    // 128  -> 161408
#define P2_SMEM 161408
#define REDSLOT 2176                      // floats per red slot

__global__ void __launch_bounds__(256, 1) __cluster_dims__(2, 1, 1) lstm_seq_h(
    const float* __restrict__ Wf, const float* __restrict__ bf,
    const float* __restrict__ Wi, const float* __restrict__ bi,
    const float* __restrict__ Wc, const float* __restrict__ bc,
    const float* __restrict__ Wo, const float* __restrict__ bo,
    float* __restrict__ out)
{
    extern __shared__ char sm[];
    float* red = (float*)(sm + RED_OFF);
    float* zbf = (float*)(sm + ZB_OFF);
    float* csm = (float*)(sm + CS_OFF);
    float* bsm = (float*)(sm + BS_OFF);

    const int tid = threadIdx.x;
    const int wid = tid >> 5, lane = tid & 31;
    const int gid = lane >> 2, tg = lane & 3;
    const int mi = wid >> 1, ns = wid & 1;
    const int cta = blockIdx.x;
    const int krank = cta & 1;                    // cluster rank == K-half
    const int nbase  = krank * 512 + (cta >> 1) * 8;        // my per-gate col base
    const int pnbase = (krank ^ 1) * 512 + (cta >> 1) * 8;  // partner col base
    const float* Wp[4] = {Wf, Wi, Wc, Wo};
    const float* bp[4] = {bf, bi, bc, bo};

    // one-time: Wh -> SMEM fp16. rows 0-31 = own cols, 32-63 = partner cols;
    // each row holds MY K-half (512 halves).
    for (int idx = tid; idx < 64 * 256; idx += 256) {
        int n = idx >> 8, k2 = idx & 255;
        int base = (n < 32) ? nbase : pnbase;
        int nn = n & 31;
        const float* wr = Wp[nn >> 3]
            + (size_t)(base + (nn & 7)) * 2048 + 1024 + krank * 512 + k2 * 2;
        float2 v = *(const float2*)wr;
        *(__half2*)(sm + WH_OFF + n * HROW2 + k2 * 4) = __floats2half2_rn(v.x, v.y);
    }
    if (tid < 32) bsm[tid] = bp[tid >> 3][nbase + (tid & 7)];
    if (tid == 0) *(volatile unsigned*)&g_flags[cta * 64] = 0u;   // replay-safe
    for (int i = tid; i < 512; i += 256) {
        csm[i] = 0.f;
        g_hh[0][(i >> 3) * H_ + nbase + (i & 7)] = __float2half(0.f);
    }
    __syncthreads();
    grid_barrier();          // h0 + flag resets visible everywhere

    const uint32_t abBase = smem_u32(sm + AB_OFF);
    const uint32_t whBase = smem_u32(sm + WH_OFF);
    const uint32_t aA = abBase
        + (mi * 16 + ((lane >> 3) & 1) * 8 + (lane & 7)) * HROW2 + (lane >> 4) * 16;
    uint32_t laneB[2];
#pragma unroll
    for (int p = 0; p < 2; p++)
        laneB[p] = whBase
            + (ns * 32 + p * 16 + (lane >> 4) * 8 + (lane & 7)) * HROW2
            + ((lane >> 3) & 1) * 16;
    const uint32_t peer_red = mapa_u32(smem_u32(red), (uint32_t)(krank ^ 1));

    for (int t = 0; t < S_; t++) {
        const __half* hcur = g_hh[t & 1];
        float* reds = red + (t & 1) * REDSLOT;
        const uint32_t peer_reds = peer_red + (uint32_t)((t & 1) * REDSLOT * 4);

        // stage my K-half of h (64 KB) in 4 cp.async commit groups
#pragma unroll
        for (int g = 0; g < 4; g++) {
#pragma unroll
            for (int j = 0; j < 4; j++) {
                int idx = tid + j * 256;
                int r = idx >> 4, c = idx & 15;
                cpa16(abBase + r * HROW2 + g * 256 + c * 16,
                      hcur + r * H_ + krank * 512 + g * 128 + c * 8);
            }
            cpa_commit();
        }

        // prefetch xg (fp16, overlaps MMA)
        float xpf[2][4];
#pragma unroll
        for (int q = 0; q < 2; q++) {
            int i = tid + q * 256;
            int b = i >> 3, r = i & 7;
            const __half* xgb = g_xg16 + ((size_t)t * B_ + b) * NG + nbase + r;
            xpf[q][0] = __half2float(__ldg(xgb));
            xpf[q][1] = __half2float(__ldg(xgb + 1024));
            xpf[q][2] = __half2float(__ldg(xgb + 2048));
            xpf[q][3] = __half2float(__ldg(xgb + 3072));
        }

        float acc[4][4];
#pragma unroll
        for (int i = 0; i < 4; i++)
#pragma unroll
            for (int k = 0; k < 4; k++) acc[i][k] = 0.f;

#pragma unroll
        for (int g = 0; g < 4; g++) {
            if (g == 0)      cpa_wait<3>();
            else if (g == 1) cpa_wait<2>();
            else if (g == 2) cpa_wait<1>();
            else             cpa_wait<0>();
            __syncthreads();
#pragma unroll
            for (int ksl = 0; ksl < 8; ksl++) {
                const uint32_t koff = (uint32_t)(g * 8 + ksl) * 32;
                uint32_t a[4], b0[4], b1[4];
                ldmx4(a,  aA + koff);
                ldmx4(b0, laneB[0] + koff);
                ldmx4(b1, laneB[1] + koff);
                mma16(acc[0], a, b0);
                mma16(acc[1], a, b0 + 2);
                mma16(acc[2], a, b1);
                mma16(acc[3], a, b1 + 2);
            }
        }

        // partials: ns=0 -> local zbf (own cols); ns=1 -> DSMEM to peer red slot
        const int b0r = mi * 16 + gid;
        if (ns == 0) {
#pragma unroll
            for (int nt = 0; nt < 4; nt++) {
                int col = nt * 8 + tg * 2;
                *(float2*)&zbf[b0r * 34 + col]       = make_float2(acc[nt][0], acc[nt][1]);
                *(float2*)&zbf[(b0r + 8) * 34 + col] = make_float2(acc[nt][2], acc[nt][3]);
            }
        } else {
#pragma unroll
            for (int nt = 0; nt < 4; nt++) {
                int col = nt * 8 + tg * 2;
                float2 f0 = make_float2(acc[nt][0], acc[nt][1]);
                float2 f1 = make_float2(acc[nt][2], acc[nt][3]);
                ull v0, v1;
                memcpy(&v0, &f0, 8);
                memcpy(&v1, &f1, 8);
                stc64(peer_reds + (uint32_t)(b0r * 34 + col) * 4, v0);
                stc64(peer_reds + (uint32_t)((b0r + 8) * 34 + col) * 4, v1);
            }
        }
        CLUSTER_SYNC();

        // gate math; c stays in SMEM; h -> fp16 global + fp32 output
        __half* hnext = g_hh[(t + 1) & 1];
#pragma unroll
        for (int q = 0; q < 2; q++) {
            int i = tid + q * 256;
            int b = i >> 3, r = i & 7;
            float zf = zbf[b * 34 + r]      + reds[b * 34 + r]      + bsm[r]      + xpf[q][0];
            float zi = zbf[b * 34 + 8 + r]  + reds[b * 34 + 8 + r]  + bsm[8 + r]  + xpf[q][1];
            float zg = zbf[b * 34 + 16 + r] + reds[b * 34 + 16 + r] + bsm[16 + r] + xpf[q][2];
            float zo = zbf[b * 34 + 24 + r] + reds[b * 34 + 24 + r] + bsm[24 + r] + xpf[q][3];
            float cc = sigm(zf) * csm[i] + sigm(zi) * tanhf(zg);
            csm[i] = cc;
            float h = sigm(zo) * tanhf(cc);
            int hc = nbase + r;
            hnext[b * H_ + hc] = __float2half(h);
            out[((size_t)b * S_ + t) * H_ + hc] = h;
            if (t == S_ - 1) {
                out[(size_t)B_ * S_ * H_ + b * H_ + hc] = h;                    // hT
                out[(size_t)B_ * S_ * H_ + (size_t)B_ * H_ + b * H_ + hc] = cc; // cT
            }
        }

        // step-end: publish my h(t+1); wait only same-parity producers
        __syncthreads();
        if (tid == 0) {
            __threadfence();
            *(volatile unsigned*)&g_flags[cta * 64] = (unsigned)(t + 1);
        }
        if (t < S_ - 1) {
            if (tid < 32) {
                const unsigned tv1 = (unsigned)(t + 1);
                const int i0 = krank + 4 * tid;          // ids i0, i0+2 (same parity)
                int need = 3;
                while (need) {
                    if ((need & 1) && *(volatile unsigned*)&g_flags[i0 * 64] >= tv1)
                        need &= ~1;
                    if ((need & 2) && *(volatile unsigned*)&g_flags[(i0 + 2) * 64] >= tv1)
                        need &= ~2;
                    if (need) __nanosleep(32);
                }
                __threadfence();
            }
            __syncthreads();
        }
    }
}

// ===========================================================================
extern "C" void kernel_launch(void* const* d_in, const int* in_sizes, int n_in,
                              void* d_out, int out_size) {
    const float* x  = (const float*)d_in[0];
    const float* Wf = (const float*)d_in[1];
    const float* bf = (const float*)d_in[2];
    const float* Wi = (const float*)d_in[3];
    const float* bi = (const float*)d_in[4];
    const float* Wc = (const float*)d_in[5];
    const float* bc = (const float*)d_in[6];
    const float* Wo = (const float*)d_in[7];
    const float* bo = (const float*)d_in[8];
    float* out = (float*)d_out;

    convert_h<<<1024, 256>>>(x, Wf, Wi, Wc, Wo);

    cudaFuncSetAttribute(xgemm_h, cudaFuncAttributeMaxDynamicSharedMemorySize, P1_SMEM);
    dim3 g1(NG / 128, (B_ * S_) / 128);            // (32, 256)
    xgemm_h<<<g1, 256, P1_SMEM>>>();

    cudaFuncSetAttribute(lstm_seq_h, cudaFuncAttributeMaxDynamicSharedMemorySize, P2_SMEM);
    lstm_seq_h<<<NCTA, 256, P2_SMEM>>>(Wf, bf, Wi, bi, Wc, bc, Wo, bo, out);
}

// round 16
// speedup vs baseline: 1.3373x; 1.0509x over previous
#include <cuda_runtime.h>
#include <cuda_fp16.h>
#include <cstdint>
#include <cstddef>
#include <cstring>

#define B_  64
#define S_  512
#define E_  1024
#define H_  1024
#define NG  4096
#define NCTA 128

typedef unsigned long long ull;

// ---------------- device scratch ----------------
__device__ __half g_xg16[(size_t)S_ * B_ * NG];   // [t][b][n] fp16 gate preacts
__device__ __half g_xh[(size_t)B_ * S_ * E_];     // x in fp16
__device__ __half g_wh[(size_t)NG * E_];          // Wx in fp16, [gate-major n][k]
__device__ __half g_hh[2][B_ * H_];               // hidden state fp16, [b][k]
__device__ unsigned g_bar_count = 0;
__device__ unsigned g_bar_gen   = 0;
__device__ unsigned g_flags[NCTA * 64];           // per-CTA step flags, 256B stride

// ---------------- helpers ----------------
__device__ __forceinline__ uint32_t smem_u32(const void* p) {
    uint32_t a;
    asm("{ .reg .u64 t; cvta.to.shared.u64 t, %1; cvt.u32.u64 %0, t; }" : "=r"(a) : "l"(p));
    return a;
}
__device__ __forceinline__ void cpa16(uint32_t saddr, const void* g) {
    asm volatile("cp.async.cg.shared.global [%0], [%1], 16;" :: "r"(saddr), "l"(g) : "memory");
}
__device__ __forceinline__ void cpa_commit() {
    asm volatile("cp.async.commit_group;" ::: "memory");
}
template<int N> __device__ __forceinline__ void cpa_wait() {
    asm volatile("cp.async.wait_group %0;" :: "n"(N) : "memory");
}
__device__ __forceinline__ void ldmx4(uint32_t* r, uint32_t addr) {
    asm volatile("ldmatrix.sync.aligned.m8n8.x4.shared.b16 {%0,%1,%2,%3}, [%4];"
        : "=r"(r[0]), "=r"(r[1]), "=r"(r[2]), "=r"(r[3]) : "r"(addr));
}
__device__ __forceinline__ void mma16(float* d, const uint32_t* a, const uint32_t* b) {
    asm("mma.sync.aligned.m16n8k16.row.col.f32.f16.f16.f32 "
        "{%0,%1,%2,%3}, {%4,%5,%6,%7}, {%8,%9}, {%0,%1,%2,%3};"
        : "+f"(d[0]), "+f"(d[1]), "+f"(d[2]), "+f"(d[3])
        : "r"(a[0]), "r"(a[1]), "r"(a[2]), "r"(a[3]), "r"(b[0]), "r"(b[1]));
}
__device__ __forceinline__ uint32_t mapa_u32(uint32_t a, uint32_t rank) {
    uint32_t r;
    asm("mapa.shared::cluster.u32 %0, %1, %2;" : "=r"(r) : "r"(a), "r"(rank));
    return r;
}
__device__ __forceinline__ void stc64(uint32_t addr, ull v) {
    asm volatile("st.shared::cluster.b64 [%0], %1;" :: "r"(addr), "l"(v) : "memory");
}
__device__ __forceinline__ void mbar_init(uint32_t a, uint32_t n) {
    asm volatile("mbarrier.init.shared.b64 [%0], %1;" :: "r"(a), "r"(n) : "memory");
}
// remote arrive on partner's mbarrier; release orders this thread's prior
// shared::cluster stores before the arrival becomes visible
__device__ __forceinline__ void mbar_arrive_cluster(uint32_t peer_addr) {
    asm volatile("mbarrier.arrive.release.cluster.shared::cluster.b64 _, [%0];"
                 :: "r"(peer_addr) : "memory");
}
#define MBAR_WAIT_CL(a, ph) do { \
    asm volatile("{\n\t.reg .pred P;\n\tWL_%=:\n\t" \
      "mbarrier.try_wait.parity.acquire.cluster.shared::cta.b64 P, [%0], %1;\n\t" \
      "@P bra.uni WD_%=;\n\tbra.uni WL_%=;\n\tWD_%=:\n\t}" \
      :: "r"((uint32_t)(a)), "r"((uint32_t)(ph)) : "memory"); } while (0)
#define CLUSTER_SYNC() do { \
    asm volatile("barrier.cluster.arrive.aligned;" ::: "memory"); \
    asm volatile("barrier.cluster.wait.aligned;"   ::: "memory"); } while (0)

// fast approx gate functions (EX2/RCP MUFU; rel err ~1e-6, negligible here)
__device__ __forceinline__ float sigmf_(float z) {
    return __fdividef(1.f, 1.f + __expf(-z));
}
__device__ __forceinline__ float tanhf_(float z) {
    return 1.f - 2.f * __fdividef(1.f, 1.f + __expf(2.f * z));
}

// Atomic barrier — used only at init (replay-safe, proven).
__device__ __forceinline__ void grid_barrier() {
    __syncthreads();
    if (threadIdx.x == 0) {
        __threadfence();
        unsigned gen = *(volatile unsigned*)&g_bar_gen;
        if (atomicAdd(&g_bar_count, 1u) == NCTA - 1) {
            atomicExch(&g_bar_count, 0u);
            __threadfence();
            atomicAdd(&g_bar_gen, 1u);
        } else {
            while (*(volatile unsigned*)&g_bar_gen == gen) __nanosleep(32);
        }
        __threadfence();
    }
    __syncthreads();
}

// ===========================================================================
// Kernel 0: convert x and Wx (x-part columns) to fp16 scratch. Unchanged.
// ===========================================================================
__global__ void convert_h(
    const float* __restrict__ x,
    const float* __restrict__ Wf, const float* __restrict__ Wi,
    const float* __restrict__ Wc, const float* __restrict__ Wo)
{
    const int stride = gridDim.x * blockDim.x;
    const int i0 = blockIdx.x * blockDim.x + threadIdx.x;
    const int NX = B_ * S_ * E_ / 2;
    for (int i = i0; i < NX; i += stride) {
        float2 v = *(const float2*)(x + (size_t)2 * i);
        ((__half2*)g_xh)[i] = __floats2half2_rn(v.x, v.y);
    }
    const int NW = NG * E_ / 2;
    for (int i = i0; i < NW; i += stride) {
        int n = i >> 9, k2 = i & 511;
        const float* Ws = (n < 1024) ? Wf : (n < 2048) ? Wi : (n < 3072) ? Wc : Wo;
        float2 v = *(const float2*)(Ws + (size_t)(n & 1023) * 2048 + k2 * 2);
        ((__half2*)g_wh)[i] = __floats2half2_rn(v.x, v.y);
    }
}

// ===========================================================================
// Phase 1: Xg = x @ Wx^T (fp16 mma, ldmatrix, cp.async 3-stage). Unchanged.
// ===========================================================================
#define P1_STAGE 36864
#define P1_SMEM  (3 * P1_STAGE)

__device__ __forceinline__ void p1_issue(uint32_t sb, int m0, int n0, int k0, int tid) {
    const int r = tid >> 3, c = tid & 7;
#pragma unroll
    for (int j = 0; j < 4; j++) {
        int rr = r + j * 32;
        cpa16(sb + rr * 144 + c * 16,         g_xh + (size_t)(m0 + rr) * E_ + k0 + c * 8);
        cpa16(sb + 18432 + rr * 144 + c * 16, g_wh + (size_t)(n0 + rr) * E_ + k0 + c * 8);
    }
    cpa_commit();
}

__global__ void __launch_bounds__(256, 2) xgemm_h()
{
    extern __shared__ char sm[];
    const uint32_t smb = smem_u32(sm);

    const int tid = threadIdx.x;
    const int wid = tid >> 5, lane = tid & 31;
    const int gid = lane >> 2, tg = lane & 3;
    const int wm = wid >> 2, wn = wid & 3;
    const int m0 = blockIdx.y * 128;
    const int n0 = blockIdx.x * 128;

    uint32_t laneA[4], laneB[2];
#pragma unroll
    for (int mi = 0; mi < 4; mi++)
        laneA[mi] = (wm * 64 + mi * 16 + ((lane >> 3) & 1) * 8 + (lane & 7)) * 144
                  + (lane >> 4) * 16;
#pragma unroll
    for (int p = 0; p < 2; p++)
        laneB[p] = 18432
                 + (wn * 32 + p * 16 + (lane >> 4) * 8 + (lane & 7)) * 144
                 + ((lane >> 3) & 1) * 16;

    float acc[4][4][4];
#pragma unroll
    for (int i = 0; i < 4; i++)
#pragma unroll
        for (int j = 0; j < 4; j++)
#pragma unroll
            for (int k = 0; k < 4; k++) acc[i][j][k] = 0.f;

    p1_issue(smb, m0, n0, 0, tid);
    p1_issue(smb + P1_STAGE, m0, n0, 64, tid);

    int st = 0;
    for (int ch = 0; ch < 16; ch++) {
        if (ch < 15) cpa_wait<1>(); else cpa_wait<0>();
        __syncthreads();
        if (ch + 2 < 16) {
            int st2 = st + 2; if (st2 >= 3) st2 -= 3;
            p1_issue(smb + st2 * P1_STAGE, m0, n0, (ch + 2) * 64, tid);
        }
        const uint32_t sb = smb + st * P1_STAGE;
#pragma unroll
        for (int kk = 0; kk < 4; kk++) {
            uint32_t a[4][4], b[2][4];
#pragma unroll
            for (int mi = 0; mi < 4; mi++) ldmx4(a[mi], sb + laneA[mi] + kk * 32);
#pragma unroll
            for (int p = 0; p < 2; p++)   ldmx4(b[p],  sb + laneB[p] + kk * 32);
#pragma unroll
            for (int mi = 0; mi < 4; mi++)
#pragma unroll
                for (int ni = 0; ni < 4; ni++)
                    mma16(acc[mi][ni], a[mi], b[ni >> 1] + (ni & 1) * 2);
        }
        if (++st >= 3) st -= 3;
    }

    // epilogue: frags -> g_xg16[t][b][n] (fp16)
#pragma unroll
    for (int mi = 0; mi < 4; mi++) {
        int row = m0 + wm * 64 + mi * 16 + gid;
        int b = row >> 9, t = row & (S_ - 1);
#pragma unroll
        for (int ni = 0; ni < 4; ni++) {
            int col = n0 + wn * 32 + ni * 8 + tg * 2;
            __half* p0 = g_xg16 + ((size_t)t * B_ + b) * NG + col;
            __half* p1 = g_xg16 + ((size_t)(t + 8) * B_ + b) * NG + col;
            *(__half2*)p0 = __floats2half2_rn(acc[mi][ni][0], acc[mi][ni][1]);
            *(__half2*)p1 = __floats2half2_rn(acc[mi][ni][2], acc[mi][ni][3]);
        }
    }
}

// ===========================================================================
// Phase 2: persistent scan, fp16 mma, cluster-pair K-split, parity-aligned
// column ownership (R14). R15 deltas:
//   - DSMEM partial exchange completes via mbarrier handshake (no cluster.sync)
//   - fast approx sigmoid/tanh (EX2/RCP MUFU)
//   - early flag publish: hnext -> sync -> flag -> out stores overlap the wait
//   - no nanosleep in hot flag poll
// ===========================================================================
#define HROW2   1040                      // 512 halves + 16B pad
#define WH_OFF  0                         // 64*1040 = 66560
#define AB_OFF  66560                     // 64*1040 -> 133120
#define RED_OFF 133120                    // 2 x [64][34] f32 -> 150528
#define ZB_OFF  150528                    // [64][34] f32 -> 159232
#define CS_OFF  159232                    // 2048 -> 161280
#define BS_OFF  161280                    // 128  -> 161408
#define MB_OFF  161408                    // 2 mbarriers (16 B) -> 161424
#define P2_SMEM 161424
#define REDSLOT 2176                      // floats per red slot

__global__ void __launch_bounds__(256, 1) __cluster_dims__(2, 1, 1) lstm_seq_h(
    const float* __restrict__ Wf, const float* __restrict__ bf,
    const float* __restrict__ Wi, const float* __restrict__ bi,
    const float* __restrict__ Wc, const float* __restrict__ bc,
    const float* __restrict__ Wo, const float* __restrict__ bo,
    float* __restrict__ out)
{
    extern __shared__ char sm[];
    float* red = (float*)(sm + RED_OFF);
    float* zbf = (float*)(sm + ZB_OFF);
    float* csm = (float*)(sm + CS_OFF);
    float* bsm = (float*)(sm + BS_OFF);

    const int tid = threadIdx.x;
    const int wid = tid >> 5, lane = tid & 31;
    const int gid = lane >> 2, tg = lane & 3;
    const int mi = wid >> 1, ns = wid & 1;
    const int cta = blockIdx.x;
    const int krank = cta & 1;                    // cluster rank == K-half
    const int nbase  = krank * 512 + (cta >> 1) * 8;        // my per-gate col base
    const int pnbase = (krank ^ 1) * 512 + (cta >> 1) * 8;  // partner col base
    const float* Wp[4] = {Wf, Wi, Wc, Wo};
    const float* bp[4] = {bf, bi, bc, bo};

    // one-time: Wh -> SMEM fp16. rows 0-31 = own cols, 32-63 = partner cols;
    // each row holds MY K-half (512 halves).
    for (int idx = tid; idx < 64 * 256; idx += 256) {
        int n = idx >> 8, k2 = idx & 255;
        int base = (n < 32) ? nbase : pnbase;
        int nn = n & 31;
        const float* wr = Wp[nn >> 3]
            + (size_t)(base + (nn & 7)) * 2048 + 1024 + krank * 512 + k2 * 2;
        float2 v = *(const float2*)wr;
        *(__half2*)(sm + WH_OFF + n * HROW2 + k2 * 4) = __floats2half2_rn(v.x, v.y);
    }
    if (tid < 32) bsm[tid] = bp[tid >> 3][nbase + (tid & 7)];
    if (tid == 0) {
        *(volatile unsigned*)&g_flags[cta * 64] = 0u;   // replay-safe
        mbar_init(smem_u32(sm + MB_OFF), 128);          // partner's 128 ns=1 threads
        mbar_init(smem_u32(sm + MB_OFF) + 8, 128);
    }
    for (int i = tid; i < 512; i += 256) {
        csm[i] = 0.f;
        g_hh[0][(i >> 3) * H_ + nbase + (i & 7)] = __float2half(0.f);
    }
    __syncthreads();
    grid_barrier();          // h0 + flag resets + mbar inits visible everywhere

    const uint32_t abBase = smem_u32(sm + AB_OFF);
    const uint32_t whBase = smem_u32(sm + WH_OFF);
    const uint32_t mbLocal = smem_u32(sm + MB_OFF);
    const uint32_t aA = abBase
        + (mi * 16 + ((lane >> 3) & 1) * 8 + (lane & 7)) * HROW2 + (lane >> 4) * 16;
    uint32_t laneB[2];
#pragma unroll
    for (int p = 0; p < 2; p++)
        laneB[p] = whBase
            + (ns * 32 + p * 16 + (lane >> 4) * 8 + (lane & 7)) * HROW2
            + ((lane >> 3) & 1) * 16;
    const uint32_t peer_red = mapa_u32(smem_u32(red), (uint32_t)(krank ^ 1));
    const uint32_t peer_mb  = mapa_u32(mbLocal, (uint32_t)(krank ^ 1));

    for (int t = 0; t < S_; t++) {
        const __half* hcur = g_hh[t & 1];
        float* reds = red + (t & 1) * REDSLOT;
        const uint32_t peer_reds = peer_red + (uint32_t)((t & 1) * REDSLOT * 4);

        // stage my K-half of h (64 KB) in 4 cp.async commit groups
#pragma unroll
        for (int g = 0; g < 4; g++) {
#pragma unroll
            for (int j = 0; j < 4; j++) {
                int idx = tid + j * 256;
                int r = idx >> 4, c = idx & 15;
                cpa16(abBase + r * HROW2 + g * 256 + c * 16,
                      hcur + r * H_ + krank * 512 + g * 128 + c * 8);
            }
            cpa_commit();
        }

        // prefetch xg (fp16, overlaps MMA)
        float xpf[2][4];
#pragma unroll
        for (int q = 0; q < 2; q++) {
            int i = tid + q * 256;
            int b = i >> 3, r = i & 7;
            const __half* xgb = g_xg16 + ((size_t)t * B_ + b) * NG + nbase + r;
            xpf[q][0] = __half2float(__ldg(xgb));
            xpf[q][1] = __half2float(__ldg(xgb + 1024));
            xpf[q][2] = __half2float(__ldg(xgb + 2048));
            xpf[q][3] = __half2float(__ldg(xgb + 3072));
        }

        float acc[4][4];
#pragma unroll
        for (int i = 0; i < 4; i++)
#pragma unroll
            for (int k = 0; k < 4; k++) acc[i][k] = 0.f;

#pragma unroll
        for (int g = 0; g < 4; g++) {
            if (g == 0)      cpa_wait<3>();
            else if (g == 1) cpa_wait<2>();
            else if (g == 2) cpa_wait<1>();
            else             cpa_wait<0>();
            __syncthreads();
#pragma unroll
            for (int ksl = 0; ksl < 8; ksl++) {
                const uint32_t koff = (uint32_t)(g * 8 + ksl) * 32;
                uint32_t a[4], b0[4], b1[4];
                ldmx4(a,  aA + koff);
                ldmx4(b0, laneB[0] + koff);
                ldmx4(b1, laneB[1] + koff);
                mma16(acc[0], a, b0);
                mma16(acc[1], a, b0 + 2);
                mma16(acc[2], a, b1);
                mma16(acc[3], a, b1 + 2);
            }
        }

        // partials: ns=0 -> local zbf; ns=1 -> DSMEM to peer red slot + arrive
        const int b0r = mi * 16 + gid;
        if (ns == 0) {
#pragma unroll
            for (int nt = 0; nt < 4; nt++) {
                int col = nt * 8 + tg * 2;
                *(float2*)&zbf[b0r * 34 + col]       = make_float2(acc[nt][0], acc[nt][1]);
                *(float2*)&zbf[(b0r + 8) * 34 + col] = make_float2(acc[nt][2], acc[nt][3]);
            }
        } else {
#pragma unroll
            for (int nt = 0; nt < 4; nt++) {
                int col = nt * 8 + tg * 2;
                float2 f0 = make_float2(acc[nt][0], acc[nt][1]);
                float2 f1 = make_float2(acc[nt][2], acc[nt][3]);
                ull v0, v1;
                memcpy(&v0, &f0, 8);
                memcpy(&v1, &f1, 8);
                stc64(peer_reds + (uint32_t)(b0r * 34 + col) * 4, v0);
                stc64(peer_reds + (uint32_t)((b0r + 8) * 34 + col) * 4, v1);
            }
            mbar_arrive_cluster(peer_mb + (uint32_t)((t & 1) * 8));
        }
        __syncthreads();                       // zbf (local) ready
        MBAR_WAIT_CL(mbLocal + (t & 1) * 8, (t >> 1) & 1);   // partner partials landed

        // gate math; c stays in SMEM; hnext FIRST, then publish, then out
        __half* hnext = g_hh[(t + 1) & 1];
        float hv[2], cv[2];
#pragma unroll
        for (int q = 0; q < 2; q++) {
            int i = tid + q * 256;
            int b = i >> 3, r = i & 7;
            float zf = zbf[b * 34 + r]      + reds[b * 34 + r]      + bsm[r]      + xpf[q][0];
            float zi = zbf[b * 34 + 8 + r]  + reds[b * 34 + 8 + r]  + bsm[8 + r]  + xpf[q][1];
            float zg = zbf[b * 34 + 16 + r] + reds[b * 34 + 16 + r] + bsm[16 + r] + xpf[q][2];
            float zo = zbf[b * 34 + 24 + r] + reds[b * 34 + 24 + r] + bsm[24 + r] + xpf[q][3];
            float cc = sigmf_(zf) * csm[i] + sigmf_(zi) * tanhf_(zg);
            csm[i] = cc;
            float h = sigmf_(zo) * tanhf_(cc);
            cv[q] = cc; hv[q] = h;
            hnext[b * H_ + nbase + r] = __float2half(h);
        }
        __syncthreads();
        if (tid == 0) {
            __threadfence();
            *(volatile unsigned*)&g_flags[cta * 64] = (unsigned)(t + 1);
        }

        // out stores overlap the producer wait
#pragma unroll
        for (int q = 0; q < 2; q++) {
            int i = tid + q * 256;
            int b = i >> 3, r = i & 7;
            int hc = nbase + r;
            out[((size_t)b * S_ + t) * H_ + hc] = hv[q];
            if (t == S_ - 1) {
                out[(size_t)B_ * S_ * H_ + b * H_ + hc] = hv[q];                   // hT
                out[(size_t)B_ * S_ * H_ + (size_t)B_ * H_ + b * H_ + hc] = cv[q]; // cT
            }
        }

        // wait only same-parity producers (tight spin, no nanosleep)
        if (t < S_ - 1) {
            if (tid < 32) {
                const unsigned tv1 = (unsigned)(t + 1);
                const int i0 = krank + 4 * tid;          // ids i0, i0+2 (same parity)
                int need = 3;
                while (need) {
                    if ((need & 1) && *(volatile unsigned*)&g_flags[i0 * 64] >= tv1)
                        need &= ~1;
                    if ((need & 2) && *(volatile unsigned*)&g_flags[(i0 + 2) * 64] >= tv1)
                        need &= ~2;
                }
                __threadfence();
            }
            __syncthreads();
        }
    }
    CLUSTER_SYNC();          // one-time: no CTA exits while partner may touch DSMEM
}

// ===========================================================================
extern "C" void kernel_launch(void* const* d_in, const int* in_sizes, int n_in,
                              void* d_out, int out_size) {
    const float* x  = (const float*)d_in[0];
    const float* Wf = (const float*)d_in[1];
    const float* bf = (const float*)d_in[2];
    const float* Wi = (const float*)d_in[3];
    const float* bi = (const float*)d_in[4];
    const float* Wc = (const float*)d_in[5];
    const float* bc = (const float*)d_in[6];
    const float* Wo = (const float*)d_in[7];
    const float* bo = (const float*)d_in[8];
    float* out = (float*)d_out;

    convert_h<<<1024, 256>>>(x, Wf, Wi, Wc, Wo);

    cudaFuncSetAttribute(xgemm_h, cudaFuncAttributeMaxDynamicSharedMemorySize, P1_SMEM);
    dim3 g1(NG / 128, (B_ * S_) / 128);            // (32, 256)
    xgemm_h<<<g1, 256, P1_SMEM>>>();

    cudaFuncSetAttribute(lstm_seq_h, cudaFuncAttributeMaxDynamicSharedMemorySize, P2_SMEM);
    lstm_seq_h<<<NCTA, 256, P2_SMEM>>>(Wf, bf, Wi, bi, Wc, bc, Wo, bo, out);
}